// round 1
// baseline (speedup 1.0000x reference)
#include <cuda_runtime.h>

// S4 DPLR layer: out = causal_conv(u, K) + D*u, where
//   K = Re(IFFT_L(atRoots)),  atRoots from the DPLR generating function,
//   causal_conv via length-2L FFT (u and K zero-padded), truncated to L.
//
// FFT strategy: four-step decomposition N = R*C with R=512.
//   Forward (output left in matrix layout [k1][k2], f = k1 + R*k2):
//     pass1: column FFTs (len R, stride C) + twiddle W_N^{-c*k1}
//     pass2: row FFTs    (len C, contiguous)
//   Inverse (consumes matrix layout, emits natural time order n = p*C + m):
//     pass1: row FFTs    (len C) + twiddle W_N^{+m*k1}
//     pass2: column FFTs (len R) -> y[p*C + m]
// atRoots is generated directly in matrix layout; the 2L forward input
// z = u + i*K is generated on the fly; the forward's permuted output feeds
// the pointwise Hermitian split/multiply and then the inverse, so no
// transpose/reorder kernels are needed anywhere.

#define L_SIZE   262144   // 2^18
#define N2L      524288   // 2^19
#define TPB      256
#define PI2      6.283185307179586f

__device__ float2 dA[N2L];   // 4 MB scratch
__device__ float2 dB[N2L];   // 4 MB scratch
__device__ float  dK[L_SIZE]; // 1 MB kernel K

static __device__ __forceinline__ float2 cmul(float2 a, float2 b) {
    return make_float2(a.x*b.x - a.y*b.y, a.x*b.y + a.y*b.x);
}
static __device__ __forceinline__ float2 cfma(float2 a, float2 b, float2 acc) {
    acc.x = fmaf(a.x, b.x, fmaf(-a.y, b.y, acc.x));
    acc.y = fmaf(a.x, b.y, fmaf( a.y, b.x, acc.y));
    return acc;
}

// Fill twiddle table tw[k] = exp(sign * 2*pi*i * k / len), k in [0, len/2)
static __device__ __forceinline__ void fill_tw(float2* tw, int half, int len, float sign) {
    const float inv = sign / (float)len;
    for (int k = threadIdx.x; k < half; k += TPB) {
        float ang = PI2 * (float)k * inv;
        float sn, cs; sincosf(ang, &sn, &cs);
        tw[k] = make_float2(cs, sn);
    }
}

// Stockham autosort radix-2 FFT, NFFT batched transforms of length LEN in smem.
// Data for batch g lives at x[g*LEN + i]. Natural-order output. Returns the
// buffer holding the result. Twiddle sign is baked into the table.
template<int LEN, int LOG_LEN, int NFFT>
static __device__ __forceinline__ float2* stockham(float2* x, float2* y, const float2* tw) {
    constexpr int HALF  = LEN >> 1;
    constexpr int TOTAL = NFFT * HALF;
    #pragma unroll 1
    for (int t = 0; t < LOG_LEN; ++t) {
        const int s = 1 << t;
        __syncthreads();
        for (int bi = threadIdx.x; bi < TOTAL; bi += TPB) {
            const int g  = bi >> (LOG_LEN - 1);
            const int b  = bi & (HALF - 1);
            const int q  = b & (s - 1);
            const int pb = b - q;              // p * s
            const int base = g * LEN;
            float2 a = x[base + q + pb];
            float2 c = x[base + q + pb + HALF];
            float2 w = tw[pb];
            float2 su = make_float2(a.x + c.x, a.y + c.y);
            float2 df = make_float2(a.x - c.x, a.y - c.y);
            y[base + q + 2*pb]     = su;
            y[base + q + 2*pb + s] = cmul(df, w);
        }
        float2* tp = x; x = y; y = tp;
    }
    __syncthreads();
    return x;
}

// ---------------------------------------------------------------------------
// Kernel 1: atRoots[j] for j in [0,L), written in matrix layout
//   dA[(j mod 512)*512 + (j div 512)]
// ---------------------------------------------------------------------------
__global__ void k_atroots(const float* __restrict__ Lre, const float* __restrict__ Lim,
                          const float* __restrict__ Pre, const float* __restrict__ Pim,
                          const float* __restrict__ Bre, const float* __restrict__ Bim,
                          const float* __restrict__ Cri, const float* __restrict__ logstep) {
    __shared__ float  sLre[64], sLim[64];
    __shared__ float2 sv0[64], sv1[64], sv2[64], sv3[64];
    const int t = threadIdx.x;
    if (t < 64) {
        float2 Pv = make_float2(Pre[t], Pim[t]);
        float2 Bv = make_float2(Bre[t], Bim[t]);
        float2 Cj = make_float2(Cri[2*t], -Cri[2*t+1]);   // conj(C)
        float2 Pj = make_float2(Pv.x, -Pv.y);             // conj(P) (Q = P)
        sLre[t] = Lre[t]; sLim[t] = Lim[t];
        sv0[t] = cmul(Cj, Bv);
        sv1[t] = cmul(Cj, Pv);
        sv2[t] = cmul(Pj, Bv);
        sv3[t] = cmul(Pj, Pv);
    }
    __syncthreads();

    const int j = blockIdx.x * TPB + t;
    const float step = expf(logstep[0]);

    float ang = -PI2 * ((float)j / (float)L_SIZE);
    float sn, cs; sincosf(ang, &sn, &cs);
    // Omega = cs + i*sn
    float2 onem = make_float2(1.f - cs, -sn);   // 1 - Omega
    float2 onep = make_float2(1.f + cs,  sn);   // 1 + Omega
    float invp = 1.f / (onep.x*onep.x + onep.y*onep.y);
    float2 cc = make_float2(2.f*onep.x*invp, -2.f*onep.y*invp);  // 2/(1+Om)
    // g = (2/step) * (1-Om) * conj(1+Om) * invp
    float2 qv = cmul(onem, make_float2(onep.x, -onep.y));
    float sfac = (2.f / step) * invp;
    float gx = qv.x * sfac, gy = qv.y * sfac;

    float2 k00 = make_float2(0,0), k01 = make_float2(0,0);
    float2 k10 = make_float2(0,0), k11 = make_float2(0,0);
    #pragma unroll
    for (int n = 0; n < 64; ++n) {
        float dx = gx - sLre[n];
        float dy = gy - sLim[n];
        float inv = 1.f / (dx*dx + dy*dy);
        float2 r = make_float2(dx*inv, -dy*inv);   // 1/(g - Lambda_n)
        k00 = cfma(r, sv0[n], k00);
        k01 = cfma(r, sv1[n], k01);
        k10 = cfma(r, sv2[n], k10);
        k11 = cfma(r, sv3[n], k11);
    }
    float2 den = make_float2(1.f + k11.x, k11.y);
    float invd = 1.f / (den.x*den.x + den.y*den.y);
    float2 num = cmul(k01, k10);
    float2 tq  = cmul(num, make_float2(den.x*invd, -den.y*invd));
    float2 at  = cmul(cc, make_float2(k00.x - tq.x, k00.y - tq.y));

    const int sidx = ((j & 511) << 9) | (j >> 9);
    dA[sidx] = at;
}

// ---------------------------------------------------------------------------
// IFFT_L (N=L, R=512, C=512)
// ---------------------------------------------------------------------------
// pass1: row FFTs (len 512, +1) of dA + twiddle exp(+2pi i m k1 / L) -> dB
__global__ void k_ifftL_p1() {
    __shared__ float2 s0[2048], s1[2048], tw[256];
    fill_tw(tw, 256, 512, 1.0f);
    const int row0 = blockIdx.x * 4;
    const float2* src = dA + row0 * 512;
    for (int i = threadIdx.x; i < 2048; i += TPB) s0[i] = src[i];
    float2* r = stockham<512, 9, 4>(s0, s1, tw);
    float2* dst = dB + row0 * 512;
    for (int i = threadIdx.x; i < 2048; i += TPB) {
        int g = i >> 9, m = i & 511;
        int k1 = row0 + g;
        int mm = (m * k1) & (L_SIZE - 1);
        float ang = PI2 * ((float)mm / (float)L_SIZE);
        float sn, cs; sincosf(ang, &sn, &cs);
        dst[i] = cmul(r[i], make_float2(cs, sn));
    }
}

// pass2: column FFTs (len 512, stride 512, +1) of dB -> K[p*512+m] = Re/L
__global__ void k_ifftL_p2() {
    __shared__ float2 s0[2048], s1[2048], tw[256];
    fill_tw(tw, 256, 512, 1.0f);
    const int c0 = blockIdx.x * 4;
    for (int i = threadIdx.x; i < 2048; i += TPB) {
        int g = i & 3, rr = i >> 2;
        s0[g*512 + rr] = dB[rr*512 + c0 + g];
    }
    float2* r = stockham<512, 9, 4>(s0, s1, tw);
    const float invL = 1.0f / (float)L_SIZE;
    for (int i = threadIdx.x; i < 2048; i += TPB) {
        int g = i & 3, p = i >> 2;
        dK[p*512 + c0 + g] = r[g*512 + p].x * invL;
    }
}

// ---------------------------------------------------------------------------
// Forward FFT_2L of z = u + i*K (zero-padded), N=2L, R=512, C=1024
// ---------------------------------------------------------------------------
// pass1: column FFTs (len 512, stride 1024, -1), z generated on the fly,
//        twiddle exp(-2pi i c k1 / 2L) -> dA[k1*1024 + c]
__global__ void k_fwd_p1(const float* __restrict__ u) {
    __shared__ float2 s0[2048], s1[2048], tw[256];
    fill_tw(tw, 256, 512, -1.0f);
    const int c0 = blockIdx.x * 4;
    for (int i = threadIdx.x; i < 2048; i += TPB) {
        int g = i & 3, rr = i >> 2;
        float2 z = make_float2(0.f, 0.f);
        if (rr < 256) {
            int idx = rr*1024 + c0 + g;     // < L
            z = make_float2(u[idx], dK[idx]);
        }
        s0[g*512 + rr] = z;
    }
    float2* r = stockham<512, 9, 4>(s0, s1, tw);
    for (int i = threadIdx.x; i < 2048; i += TPB) {
        int g = i & 3, k1 = i >> 2;
        int c = c0 + g;
        int mm = (c * k1) & (N2L - 1);
        float ang = -PI2 * ((float)mm / (float)N2L);
        float sn, cs; sincosf(ang, &sn, &cs);
        dA[k1*1024 + c] = cmul(r[g*512 + k1], make_float2(cs, sn));
    }
}

// pass2: row FFTs (len 1024, -1) of dA -> dB  (Z in matrix layout)
__global__ void k_fwd_p2() {
    __shared__ float2 s0[2048], s1[2048], tw[512];
    fill_tw(tw, 512, 1024, -1.0f);
    const int row0 = blockIdx.x * 2;
    const float2* src = dA + row0 * 1024;
    for (int i = threadIdx.x; i < 2048; i += TPB) s0[i] = src[i];
    float2* r = stockham<1024, 10, 2>(s0, s1, tw);
    float2* dst = dB + row0 * 1024;
    for (int i = threadIdx.x; i < 2048; i += TPB) dst[i] = r[i];
}

// ---------------------------------------------------------------------------
// Pointwise: split Z into U (spectrum of u) and Kd (spectrum of K) via
// Hermitian symmetry, Y = U * Kd. Matrix layout: f = k1 + 512*k2 at
// [k1*1024 + k2]; partner 2L-f at (k1==0 ? (0,(1024-k2)&1023) : (512-k1, 1023-k2)).
// ---------------------------------------------------------------------------
__global__ void k_pointwise() {
    const int idx = blockIdx.x * TPB + threadIdx.x;
    const int k1 = idx >> 10, k2 = idx & 1023;
    int pk1, pk2;
    if (k1 == 0) { pk1 = 0;        pk2 = (1024 - k2) & 1023; }
    else         { pk1 = 512 - k1; pk2 = 1023 - k2; }
    float2 Z  = dB[idx];
    float2 Zp = dB[pk1*1024 + pk2];
    // U  = (Z + conj(Zp)) / 2 ; Kd = (Z - conj(Zp)) / (2i)
    float2 U  = make_float2(0.5f*(Z.x + Zp.x), 0.5f*(Z.y - Zp.y));
    float2 Kd = make_float2(0.5f*(Z.y + Zp.y), -0.5f*(Z.x - Zp.x));
    dA[idx] = cmul(U, Kd);
}

// ---------------------------------------------------------------------------
// Inverse FFT_2L of Y (matrix layout in dA) -> natural-order real output
// ---------------------------------------------------------------------------
// pass1: row FFTs (len 1024, +1) + twiddle exp(+2pi i m k1 / 2L) -> dB
__global__ void k_inv_p1() {
    __shared__ float2 s0[2048], s1[2048], tw[512];
    fill_tw(tw, 512, 1024, 1.0f);
    const int row0 = blockIdx.x * 2;
    const float2* src = dA + row0 * 1024;
    for (int i = threadIdx.x; i < 2048; i += TPB) s0[i] = src[i];
    float2* r = stockham<1024, 10, 2>(s0, s1, tw);
    float2* dst = dB + row0 * 1024;
    for (int i = threadIdx.x; i < 2048; i += TPB) {
        int g = i >> 10, m = i & 1023;
        int k1 = row0 + g;
        int mm = (m * k1) & (N2L - 1);
        float ang = PI2 * ((float)mm / (float)N2L);
        float sn, cs; sincosf(ang, &sn, &cs);
        dst[i] = cmul(r[i], make_float2(cs, sn));
    }
}

// pass2: column FFTs (len 512, stride 1024, +1); y[p*1024+m] for p<256
//        out[n] = Re(y[n])/(2L) + D*u[n]
__global__ void k_inv_p2(const float* __restrict__ u, const float* __restrict__ Dp,
                         float* __restrict__ out) {
    __shared__ float2 s0[2048], s1[2048], tw[256];
    fill_tw(tw, 256, 512, 1.0f);
    const int c0 = blockIdx.x * 4;
    for (int i = threadIdx.x; i < 2048; i += TPB) {
        int g = i & 3, rr = i >> 2;
        s0[g*512 + rr] = dB[rr*1024 + c0 + g];
    }
    float2* r = stockham<512, 9, 4>(s0, s1, tw);
    const float sc = 1.0f / (float)N2L;
    const float Dv = Dp[0];
    for (int i = threadIdx.x; i < 1024; i += TPB) {  // p < 256 => n < L
        int g = i & 3, p = i >> 2;
        int n = p*1024 + c0 + g;
        out[n] = fmaf(Dv, u[n], r[g*512 + p].x * sc);
    }
}

// ---------------------------------------------------------------------------
extern "C" void kernel_launch(void* const* d_in, const int* in_sizes, int n_in,
                              void* d_out, int out_size) {
    (void)in_sizes; (void)n_in; (void)out_size;
    const float* u   = (const float*)d_in[0];
    const float* Lre = (const float*)d_in[1];
    const float* Lim = (const float*)d_in[2];
    const float* Pre = (const float*)d_in[3];
    const float* Pim = (const float*)d_in[4];
    const float* Bre = (const float*)d_in[5];
    const float* Bim = (const float*)d_in[6];
    const float* Cri = (const float*)d_in[7];
    const float* Dp  = (const float*)d_in[8];
    const float* ls  = (const float*)d_in[9];
    float* out = (float*)d_out;

    k_atroots <<<L_SIZE / TPB, TPB>>>(Lre, Lim, Pre, Pim, Bre, Bim, Cri, ls);
    k_ifftL_p1<<<128, TPB>>>();
    k_ifftL_p2<<<128, TPB>>>();
    k_fwd_p1  <<<256, TPB>>>(u);
    k_fwd_p2  <<<256, TPB>>>();
    k_pointwise<<<N2L / TPB, TPB>>>();
    k_inv_p1  <<<256, TPB>>>();
    k_inv_p2  <<<256, TPB>>>(u, Dp, out);
}